// round 11
// baseline (speedup 1.0000x reference)
#include <cuda_runtime.h>
#include <cuda_fp16.h>
#include <cstdint>
#include <math.h>

#define BSZ   256
#define NLEAF 64
#define SZ    512
#define D2    1024
#define GN    2560
#define RMAX  64

#define BM    64
#define BN    80
#define NTH   512

// spinn smem layout (bytes): A(64K, also Gs0/Gs1) | B1(Wl) | B2(Wr) | id tables
#define AOFF   0
#define B1OFF  65536
#define B2OFF  147456
#define CTRL   229376
#define SMEM_TOTAL (CTRL + 1792)     // 231168 <= 232448 opt-in max

// pr smem: 3 A stages (80B-stride rows) + resident B
#define PRA    0
#define PRASTG 10240                 // 128 rows x 80B
#define PRB    30720
#define PR_SMEM (PRB + 81920)        // 112640 (2 CTAs/SM)

// ---------------- device scratch ----------------
__device__ __half   g_h[BSZ][129][SZ];      // 0..63 leaves, 64..127 results, 128 zero
__device__ float    g_c[BSZ][RMAX + 1][SZ];
__device__ float    g_hf[BSZ][RMAX][SZ];
__device__ __half   g_Wt[(size_t)GN * D2];  // [dc][k] gate-interleaved, transposed
__device__ float    g_bias[GN];
__device__ __half   g_PR8[(size_t)BSZ * NLEAF * 4096]; // leaf @ Wr, padded: [row][j][8]
__device__ int      g_lop[BSZ * RMAX];
__device__ int      g_rop[BSZ * RMAX];
__device__ int      g_nred[BSZ];
__device__ int      g_nredmax[4];
__device__ int      g_top[BSZ];
__device__ int      g_badR[RMAX];
__device__ unsigned g_bar4[4];

__device__ __forceinline__ float sigm(float x) { return 1.0f / (1.0f + expf(-x)); }

// ---------------- PTX helpers ----------------
__device__ __forceinline__ void cp16(uint32_t sdst, const void* gsrc) {
    asm volatile("cp.async.cg.shared.global [%0], [%1], 16;\n" :: "r"(sdst), "l"(gsrc));
}
__device__ __forceinline__ void cp_commit() { asm volatile("cp.async.commit_group;\n" ::); }
template <int N> __device__ __forceinline__ void cp_wait() {
    asm volatile("cp.async.wait_group %0;\n" :: "n"(N));
}
__device__ __forceinline__ void ldsm4(uint32_t* r, uint32_t addr) {
    asm volatile("ldmatrix.sync.aligned.m8n8.x4.shared.b16 {%0,%1,%2,%3},[%4];\n"
                 : "=r"(r[0]), "=r"(r[1]), "=r"(r[2]), "=r"(r[3]) : "r"(addr));
}
__device__ __forceinline__ void ldsm2(uint32_t& r0, uint32_t& r1, uint32_t addr) {
    asm volatile("ldmatrix.sync.aligned.m8n8.x2.shared.b16 {%0,%1},[%2];\n"
                 : "=r"(r0), "=r"(r1) : "r"(addr));
}
__device__ __forceinline__ void mma16816(float* c, const uint32_t* a, uint32_t b0, uint32_t b1) {
    asm volatile(
        "mma.sync.aligned.m16n8k16.row.col.f32.f16.f16.f32 "
        "{%0,%1,%2,%3},{%4,%5,%6,%7},{%8,%9},{%0,%1,%2,%3};\n"
        : "+f"(c[0]), "+f"(c[1]), "+f"(c[2]), "+f"(c[3])
        : "r"(a[0]), "r"(a[1]), "r"(a[2]), "r"(a[3]), "r"(b0), "r"(b1));
}
__device__ __forceinline__ void bar_arrive_release(unsigned* addr) {
    asm volatile("red.release.gpu.global.add.u32 [%0], %1;" :: "l"(addr), "r"(1u) : "memory");
}
__device__ __forceinline__ unsigned ld_relaxed(const unsigned* addr) {
    unsigned v;
    asm volatile("ld.relaxed.gpu.global.u32 %0, [%1];" : "=r"(v) : "l"(addr) : "memory");
    return v;
}
__device__ __forceinline__ unsigned ld_acquire(const unsigned* addr) {
    unsigned v;
    asm volatile("ld.acquire.gpu.global.u32 %0, [%1];" : "=r"(v) : "l"(addr) : "memory");
    return v;
}

// ---------------- setup: leaves->fp16 + zero slots ----------------
__global__ void setup_kernel(const float* __restrict__ buffers) {
    int bid = blockIdx.x, tid = threadIdx.x;
    if (bid < 8192) {
        int i4 = (bid * 256 + tid) * 4;
        int b = i4 >> 15, rem = i4 & 32767;
        int r = rem >> 9, j = rem & 511;
        float4 v = *(const float4*)(buffers + ((size_t)b << 16) + ((size_t)r << 10) + j);
        __half2 h0 = __floats2half2_rn(v.x, v.y);
        __half2 h1 = __floats2half2_rn(v.z, v.w);
        *(uint2*)&g_h[b][r][j] = make_uint2(*(uint32_t*)&h0, *(uint32_t*)&h1);
    } else {
        int i = (bid - 8192) * 256 + tid;
        int b = i >> 9, j = i & 511;
        g_h[b][128][j] = __half(0.0f);
        g_c[b][RMAX][j] = 0.0f;
    }
}

// ---------------- weights: fp32 -> fp16, gate-interleave + transpose ----------------
__global__ void convert_w_kernel(const float* __restrict__ Wl,
                                 const float* __restrict__ Wr,
                                 const float* __restrict__ bl) {
    __shared__ float tile[40][33];
    int tid = threadIdx.x;
    int dcb = blockIdx.x >> 5;
    int kb  = blockIdx.x & 31;
    int dc0 = dcb * 40, k0 = kb * 32, j0 = dcb * 8;
    for (int e = tid; e < 1280; e += 256) {
        int jj = e & 7, g = (e >> 3) % 5, k = e / 40;
        int sc = g * SZ + j0 + jj;
        int kk = k0 + k;
        float v = (kk < SZ) ? Wl[(size_t)kk * GN + sc] : Wr[(size_t)(kk - SZ) * GN + sc];
        tile[5 * jj + g][k] = v;
    }
    __syncthreads();
    for (int e = tid; e < 1280; e += 256) {
        int kk = e & 31, dcl = e >> 5;
        g_Wt[((size_t)(dc0 + dcl) << 10) + k0 + kk] = __float2half(tile[dcl][kk]);
    }
    if (kb == 0 && tid < 40) {
        int dc = dc0 + tid, j = dc / 5, g = dc % 5;
        g_bias[dc] = bl[g * SZ + j];
    }
}

// ---------------- schedule ----------------
__global__ void schedule_kernel(const int* __restrict__ trans, int T) {
    __shared__ int st[136][33];
    int lt = threadIdx.x;
    int b = blockIdx.x * 32 + lt;
    if (blockIdx.x == 0 && lt < 4) g_bar4[lt] = 0;
    for (int i = 0; i < 136; i++) st[i][lt] = 128;
    int ptr = 0, bptr = 0, nr = 0;
    for (int t = 0; t < T; t++) {
        int tr = trans[b * T + t];
        if (tr == 0) {
            int n = (bptr < NLEAF - 1) ? bptr : (NLEAF - 1);
            int wp = ptr; if (wp < 0) wp = 0; if (wp > 130) wp = 130;
            st[wp][lt] = n;
            ptr++; bptr++;
        } else if (tr == 1) {
            int lp = ptr - 2; if (lp < 0) lp = 0;
            int rp = ptr - 1; if (rp < 0) rp = 0;
            if (nr < RMAX) {
                int lv = st[lp][lt], rv = st[rp][lt];
                g_lop[(b << 6) + nr] = lv;
                g_rop[(b << 6) + nr] = rv;
                if (rv >= 64 && rv < 128) atomicOr(&g_badR[nr], 1);
                st[lp][lt] = 64 + nr;
                nr++;
            }
            ptr--;
        }
    }
    for (int i = nr; i < RMAX; i++) {
        g_lop[(b << 6) + i] = 128;
        g_rop[(b << 6) + i] = 128;
    }
    g_nred[b] = nr;
    atomicMax(&g_nredmax[b >> 6], nr);
    int tp = ptr - 1; if (tp < 0) tp = 0; if (tp > 130) tp = 130;
    g_top[b] = st[tp][lt];
}

// ---------------- PR precompute: PR8[row][j][0..4] = leaf_h[row] @ Wr ----------------
__global__ __launch_bounds__(256, 2) void pr_kernel() {
    extern __shared__ __align__(16) char smem[];
    uint32_t sb = (uint32_t)__cvta_generic_to_shared(smem);
    int tid = threadIdx.x, warp = tid >> 5, lane = tid & 31;
    int wm = warp >> 1, wn = warp & 1;
    int wc = wn * 40;
    int row0 = blockIdx.y * 128, col0 = blockIdx.x * 80;

    auto issueA = [&](int s) {
        uint32_t base = sb + PRA + (uint32_t)(s % 3) * PRASTG;
        #pragma unroll
        for (int j = 0; j < 2; j++) {
            int idx = tid + j * 256;
            int r = idx >> 2, c = idx & 3;
            int grow = row0 + r;
            cp16(base + (uint32_t)(r * 80 + c * 16),
                 &g_h[grow >> 6][grow & 63][s * 32 + c * 8]);
        }
    };

    for (int idx = tid; idx < 5120; idx += 256) {
        int r = idx >> 6, c = idx & 63;
        cp16(sb + PRB + (uint32_t)(r * 1024 + (((c ^ (r & 7)) << 4))),
             (const char*)g_Wt + ((size_t)(col0 + r) << 11) + 1024 + c * 16);
    }
    issueA(0); cp_commit();
    issueA(1); cp_commit();

    float acc[2][5][4];
    #pragma unroll
    for (int su = 0; su < 2; su++)
        #pragma unroll
        for (int f = 0; f < 5; f++)
            #pragma unroll
            for (int q = 0; q < 4; q++) acc[su][f][q] = 0.0f;

    int fr0 = wm * 32 + (lane & 7) + ((lane >> 3) & 1) * 8;
    int fr1 = fr0 + 16;
    int sel4 = (lane >> 4) & 1, sel3 = (lane >> 3) & 1;

    for (int s = 0; s < 16; s++) {
        cp_wait<1>();
        __syncthreads();
        uint32_t ab = sb + PRA + (uint32_t)(s % 3) * PRASTG;
        #pragma unroll
        for (int i = 0; i < 2; i++) {
            int ca = i * 2 + sel4;
            uint32_t a0[4], a1[4];
            ldsm4(a0, ab + (uint32_t)(fr0 * 80 + ca * 16));
            ldsm4(a1, ab + (uint32_t)(fr1 * 80 + ca * 16));
            int cbu = (s * 2 + i) * 2 + sel3;
            int br01 = wc + (0 + sel4) * 8 + (lane & 7);
            int br23 = wc + (2 + sel4) * 8 + (lane & 7);
            int br4  = wc + 32 + (lane & 7);
            uint32_t b01[4], b23[4], b4a, b4b;
            ldsm4(b01, sb + PRB + (uint32_t)(br01 * 1024 + (((cbu ^ (br01 & 7)) << 4))));
            ldsm4(b23, sb + PRB + (uint32_t)(br23 * 1024 + (((cbu ^ (br23 & 7)) << 4))));
            ldsm2(b4a, b4b, sb + PRB + (uint32_t)(br4 * 1024 + (((cbu ^ (br4 & 7)) << 4))));
            mma16816(acc[0][0], a0, b01[0], b01[1]); mma16816(acc[1][0], a1, b01[0], b01[1]);
            mma16816(acc[0][1], a0, b01[2], b01[3]); mma16816(acc[1][1], a1, b01[2], b01[3]);
            mma16816(acc[0][2], a0, b23[0], b23[1]); mma16816(acc[1][2], a1, b23[0], b23[1]);
            mma16816(acc[0][3], a0, b23[2], b23[3]); mma16816(acc[1][3], a1, b23[2], b23[3]);
            mma16816(acc[0][4], a0, b4a, b4b);       mma16816(acc[1][4], a1, b4a, b4b);
        }
        if (s + 2 < 16) issueA(s + 2);
        cp_commit();
    }
    cp_wait<0>();

    int gp = lane >> 2, t4 = lane & 3;
    #pragma unroll
    for (int su = 0; su < 2; su++)
        #pragma unroll
        for (int f = 0; f < 5; f++) {
            int r0 = row0 + wm * 32 + su * 16 + gp;
            int dc = col0 + wc + f * 8 + t4 * 2;
            int j = dc / 5, g = dc - 5 * j;
            __half h0 = __float2half(acc[su][f][0]);
            __half h1 = __float2half(acc[su][f][1]);
            __half h2 = __float2half(acc[su][f][2]);
            __half h3 = __float2half(acc[su][f][3]);
            size_t a0 = ((size_t)r0 << 12) + j * 8 + g;
            size_t a1 = ((size_t)(r0 + 8) << 12) + j * 8 + g;
            if (g < 4 && (g & 1) == 0) {
                *(__half2*)&g_PR8[a0] = __halves2half2(h0, h1);
                *(__half2*)&g_PR8[a1] = __halves2half2(h2, h3);
            } else if (g < 4) {
                g_PR8[a0] = h0; g_PR8[a0 + 1] = h1;
                g_PR8[a1] = h2; g_PR8[a1 + 1] = h3;
            } else {                     // g == 4: second gate wraps to unit j+1
                g_PR8[a0] = h0; g_PR8[((size_t)r0 << 12) + (j + 1) * 8] = h1;
                g_PR8[a1] = h2; g_PR8[((size_t)(r0 + 8) << 12) + (j + 1) * 8] = h3;
            }
        }
}

// ---------------- persistent SPINN kernel ----------------
// grid (32, 4) = 128 CTAs, 512 threads = 16 warps: kg(4) x wm(2) x wn(2)
__global__ __launch_bounds__(NTH, 1) void spinn_kernel(const float* __restrict__ buffers, int RL) {
    extern __shared__ __align__(16) char smem[];
    uint32_t sb = (uint32_t)__cvta_generic_to_shared(smem);
    int* s_lop = (int*)(smem + CTRL);          // [2][64]
    int* s_rop = (int*)(smem + CTRL + 512);    // [2][64]
    int* s_val = (int*)(smem + CTRL + 1024);   // [2][64]
    int* s_top = (int*)(smem + CTRL + 1536);   // [64]

    int tid = threadIdx.x, warp = tid >> 5, lane = tid & 31;
    int kg = warp >> 2, wm = (warp >> 1) & 1, wn = warp & 1;
    int wr = wm * 32, wc = wn * 40;
    int row0 = blockIdx.y * BM, col0 = blockIdx.x * BN;
    int by = blockIdx.y;

    // resident B1 (Wl) and B2 (Wr): 80 rows x 1024B each, XOR-8 swizzle
    for (int idx = tid; idx < 80 * 64; idx += NTH) {
        int r = idx >> 6, c = idx & 63;
        uint32_t dsw = (uint32_t)(r * 1024 + (((c ^ (r & 7)) << 4)));
        const char* src = (const char*)g_Wt + ((size_t)(col0 + r) << 11) + c * 16;
        cp16(sb + B1OFF + dsw, src);
        cp16(sb + B2OFF + dsw, src + 1024);
    }
    cp_commit(); cp_wait<0>();

    int RLg = g_nredmax[by];
    if (RLg > RL) RLg = RL;

    int jl = tid & 15;
    int jg0 = blockIdx.x * 16 + jl;
    float bias[5];
    #pragma unroll
    for (int g = 0; g < 5; g++) bias[g] = g_bias[col0 + jl * 5 + g];

    int arow = tid >> 3, ac0 = tid & 7;
    int fr0 = wr + (lane & 7) + ((lane >> 3) & 1) * 8;
    int fr1 = fr0 + 16;
    int sel4 = (lane >> 4) & 1, sel3 = (lane >> 3) & 1;
    int gp = lane >> 2, t4 = lane & 3;

    float (*Gs0)[84] = (float (*)[84])smem;
    float (*Gs1)[84] = (float (*)[84])(smem + 32768);

    if (tid < 64) {
        int b = row0 + tid;
        s_lop[tid] = g_lop[b << 6];
        s_rop[tid] = g_rop[b << 6];
        s_val[tid] = (0 < g_nred[b]) ? 1 : 0;
        s_top[tid] = g_top[b];
    }
    __syncthreads();

    for (int k = 0; k < RLg; k++) {
        int par = k & 1;
        int skipf = (g_badR[k] == 0);

        // A load: two 32KB halves, separate commit groups
        auto loadA = [&](int useR) {
            int id = (useR ? s_rop : s_lop)[par * 64 + arow];
            const __half* src = &g_h[row0 + arow][id][0];
            #pragma unroll
            for (int j = 0; j < 4; j++) {
                int c = ac0 + j * 8;
                cp16(sb + AOFF + (uint32_t)(arow * 1024 + (((c ^ (arow & 7)) << 4))),
                     src + c * 8);
            }
            cp_commit();
            #pragma unroll
            for (int j = 4; j < 8; j++) {
                int c = ac0 + j * 8;
                cp16(sb + AOFF + (uint32_t)(arow * 1024 + (((c ^ (arow & 7)) << 4))),
                     src + c * 8);
            }
            cp_commit();
        };

        loadA(0);

        // ---- prefetch epilogue operands (latency hidden behind GEMM) ----
        float lcv[2], rcv[2], tab[2][5];
        #pragma unroll
        for (int i = 0; i < 2; i++) {
            int r = (tid >> 4) + 32 * i;
            int b = row0 + r;
            int lid = s_lop[par * 64 + r], rid = s_rop[par * 64 + r];
            lcv[i] = (lid < 64) ? buffers[((size_t)b << 16) + ((size_t)lid << 10) + SZ + jg0]
                                : g_c[b][(lid == 128) ? RMAX : (lid - 64)][jg0];
            rcv[i] = (rid < 64) ? buffers[((size_t)b << 16) + ((size_t)rid << 10) + SZ + jg0]
                                : g_c[b][(rid == 128) ? RMAX : (rid - 64)][jg0];
            #pragma unroll
            for (int g = 0; g < 5; g++) tab[i][g] = 0.0f;
            if (skipf && rid < 64) {
                uint4 raw = *(const uint4*)&g_PR8[(((size_t)((b << 6) + rid)) << 12)
                                                  + (size_t)jg0 * 8];
                __half2* hp = (__half2*)&raw;
                tab[i][0] = __low2float(hp[0]);  tab[i][1] = __high2float(hp[0]);
                tab[i][2] = __low2float(hp[1]);  tab[i][3] = __high2float(hp[1]);
                tab[i][4] = __low2float(hp[2]);
            }
        }

        // ---- next-step id tables (static schedule; overlap with GEMM) ----
        if (tid < 64) {
            int kn = k + 1;
            int b = row0 + tid;
            int lop = 128, rop = 128, vv = 0;
            if (kn < RMAX) {
                lop = g_lop[(b << 6) + kn];
                rop = g_rop[(b << 6) + kn];
                vv  = (kn < g_nred[b]) ? 1 : 0;
            }
            int np = par ^ 1;
            s_lop[np * 64 + tid] = lop;
            s_rop[np * 64 + tid] = rop;
            s_val[np * 64 + tid] = vv;
        }

        float acc[2][5][4];
        #pragma unroll
        for (int su = 0; su < 2; su++)
            #pragma unroll
            for (int f = 0; f < 5; f++)
                #pragma unroll
                for (int q = 0; q < 4; q++) acc[su][f][q] = 0.0f;

        // K-chunk map: ca = i*8 + kg*2 + sel — every kg owns chunks in both halves
        auto pass = [&](uint32_t boff, int i0, int i1) {
            #pragma unroll
            for (int i = i0; i < i1; i++) {
                int ca = i * 8 + kg * 2 + sel4;
                uint32_t a0[4], a1[4];
                ldsm4(a0, sb + AOFF + (uint32_t)(fr0 * 1024 + (((ca ^ (fr0 & 7)) << 4))));
                ldsm4(a1, sb + AOFF + (uint32_t)(fr1 * 1024 + (((ca ^ (fr1 & 7)) << 4))));
                int cbu = i * 8 + kg * 2 + sel3;
                int br01 = wc + (0 + sel4) * 8 + (lane & 7);
                int br23 = wc + (2 + sel4) * 8 + (lane & 7);
                int br4  = wc + 32 + (lane & 7);
                uint32_t b01[4], b23[4], b4a, b4b;
                ldsm4(b01, sb + boff + (uint32_t)(br01 * 1024 + (((cbu ^ (br01 & 7)) << 4))));
                ldsm4(b23, sb + boff + (uint32_t)(br23 * 1024 + (((cbu ^ (br23 & 7)) << 4))));
                ldsm2(b4a, b4b, sb + boff + (uint32_t)(br4 * 1024 + (((cbu ^ (br4 & 7)) << 4))));
                mma16816(acc[0][0], a0, b01[0], b01[1]); mma16816(acc[1][0], a1, b01[0], b01[1]);
                mma16816(acc[0][1], a0, b01[2], b01[3]); mma16816(acc[1][1], a1, b01[2], b01[3]);
                mma16816(acc[0][2], a0, b23[0], b23[1]); mma16816(acc[1][2], a1, b23[0], b23[1]);
                mma16816(acc[0][3], a0, b23[2], b23[3]); mma16816(acc[1][3], a1, b23[2], b23[3]);
                mma16816(acc[0][4], a0, b4a, b4b);       mma16816(acc[1][4], a1, b4a, b4b);
            }
        };

        // half0 compute overlaps half1 in-flight
        cp_wait<1>();
        __syncthreads();
        pass(B1OFF, 0, 4);
        cp_wait<0>();
        __syncthreads();
        pass(B1OFF, 4, 8);

        if (!skipf) {                    // generic fallback: rh @ Wr in-step
            __syncthreads();
            loadA(1);
            cp_wait<0>();
            __syncthreads();
            pass(B2OFF, 0, 8);
        }
        __syncthreads();

        // ---- K-split reduction: 2 buffers, 2 sync points ----
        if (kg >= 2) {
            float (*G)[84] = (kg == 3) ? Gs0 : Gs1;
            #pragma unroll
            for (int su = 0; su < 2; su++)
                #pragma unroll
                for (int f = 0; f < 5; f++) {
                    int rr = wr + su * 16 + gp, cc = wc + f * 8 + t4 * 2;
                    G[rr][cc]         = acc[su][f][0];
                    G[rr][cc + 1]     = acc[su][f][1];
                    G[rr + 8][cc]     = acc[su][f][2];
                    G[rr + 8][cc + 1] = acc[su][f][3];
                }
        }
        __syncthreads();
        if (kg < 2) {
            float (*G)[84] = (kg == 1) ? Gs0 : Gs1;
            #pragma unroll
            for (int su = 0; su < 2; su++)
                #pragma unroll
                for (int f = 0; f < 5; f++) {
                    int rr = wr + su * 16 + gp, cc = wc + f * 8 + t4 * 2;
                    G[rr][cc]         += acc[su][f][0];
                    G[rr][cc + 1]     += acc[su][f][1];
                    G[rr + 8][cc]     += acc[su][f][2];
                    G[rr + 8][cc + 1] += acc[su][f][3];
                }
        }
        __syncthreads();

        // ---- LSTM epilogue ----
        #pragma unroll
        for (int i = 0; i < 2; i++) {
            int r = (tid >> 4) + 32 * i;
            if (s_val[par * 64 + r]) {
                int b  = row0 + r;
                int cb = jl * 5;
                float a  = Gs0[r][cb + 0] + Gs1[r][cb + 0] + bias[0] + tab[i][0];
                float ii = Gs0[r][cb + 1] + Gs1[r][cb + 1] + bias[1] + tab[i][1];
                float f1 = Gs0[r][cb + 2] + Gs1[r][cb + 2] + bias[2] + tab[i][2];
                float f2 = Gs0[r][cb + 3] + Gs1[r][cb + 3] + bias[3] + tab[i][3];
                float o  = Gs0[r][cb + 4] + Gs1[r][cb + 4] + bias[4] + tab[i][4];
                float cc = tanhf(a) * sigm(ii) + sigm(f1) * lcv[i] + sigm(f2) * rcv[i];
                float hh = sigm(o) * tanhf(cc);
                g_h[b][64 + k][jg0] = __float2half(hh);
                g_c[b][k][jg0]      = cc;
                if (s_top[r] == 64 + k) g_hf[b][k][jg0] = hh;   // only the final top is read
            }
        }

        // ---- row-group barrier: release arrival + acquire poll ----
        __syncthreads();
        if (tid == 0) {
            bar_arrive_release(&g_bar4[by]);
            unsigned tgt = (unsigned)(32 * (k + 1));
            while (ld_relaxed(&g_bar4[by]) < tgt) { }
            (void)ld_acquire(&g_bar4[by]);
        }
        __syncthreads();
    }
}

// ---------------- final gather ----------------
__global__ void final_kernel(const float* __restrict__ buffers, float* __restrict__ out) {
    int i = blockIdx.x * blockDim.x + threadIdx.x;
    if (i >= BSZ * SZ) return;
    int b = i / SZ, j = i % SZ;
    int op = g_top[b];
    float v;
    if (op < 64)       v = buffers[((size_t)b << 16) + ((size_t)op << 10) + j];
    else if (op < 128) v = g_hf[b][op - 64][j];
    else               v = 0.0f;
    out[i] = v;
}

// ---------------- launch ----------------
extern "C" void kernel_launch(void* const* d_in, const int* in_sizes, int n_in,
                              void* d_out, int out_size) {
    const float* buffers = (const float*)d_in[0];
    const int*   trans   = (const int*)d_in[1];
    const float* Wl      = (const float*)d_in[2];
    const float* Wr      = (const float*)d_in[3];
    const float* bl      = (const float*)d_in[4];
    float*       out     = (float*)d_out;

    int T  = in_sizes[1] / BSZ;
    int RL = (T + 1) / 2;
    if (RL > RMAX) RL = RMAX;

    static int attr_done = 0;
    if (!attr_done) {
        cudaFuncSetAttribute(spinn_kernel, cudaFuncAttributeMaxDynamicSharedMemorySize,
                             SMEM_TOTAL);
        cudaFuncSetAttribute(pr_kernel, cudaFuncAttributeMaxDynamicSharedMemorySize,
                             PR_SMEM);
        attr_done = 1;
    }

    schedule_kernel<<<8, 32>>>(trans, T);
    setup_kernel<<<8192 + 512, 256>>>(buffers);
    convert_w_kernel<<<2048, 256>>>(Wl, Wr, bl);

    dim3 prgrid(GN / 80, (BSZ * NLEAF) / 128);    // (32, 128)
    pr_kernel<<<prgrid, 256, PR_SMEM>>>();

    dim3 grid(GN / BN, BSZ / BM);                 // (32, 4) = 128 CTAs
    spinn_kernel<<<grid, NTH, SMEM_TOTAL>>>(buffers, RL);

    final_kernel<<<(BSZ * SZ + 255) / 256, 256>>>(buffers, out);
}

// round 14
// speedup vs baseline: 1.1959x; 1.1959x over previous
#include <cuda_runtime.h>
#include <cuda_fp16.h>
#include <cstdint>
#include <math.h>

#define BSZ   256
#define NLEAF 64
#define SZ    512
#define D2    1024
#define GN    2560
#define RMAX  64

#define BM    64
#define BN    80
#define NTH   512

// spinn smem layout (bytes): A(64K, Gs fallback) | B1(Wl) | B2(Wr / Gs fast) | id tables
#define AOFF   0
#define B1OFF  65536
#define B2OFF  147456
#define CTRL   229376
#define SMEM_TOTAL (CTRL + 1792)     // 231168 <= 232448 opt-in max

// pr smem: 3 A stages (80B-stride rows) + resident B
#define PRA    0
#define PRASTG 10240                 // 128 rows x 80B
#define PRB    30720
#define PR_SMEM (PRB + 81920)        // 112640 (2 CTAs/SM)

// ---------------- device scratch ----------------
__device__ __half   g_h[BSZ][129][SZ];      // 0..63 leaves, 64..127 results, 128 zero
__device__ float    g_c[BSZ][RMAX + 1][SZ];
__device__ float    g_hf[BSZ][RMAX][SZ];
__device__ __half   g_Wt[(size_t)GN * D2];  // [dc][k] gate-interleaved, transposed
__device__ float    g_bias[GN];
__device__ __half   g_PRh[(size_t)BSZ * NLEAF * GN]; // leaf @ Wr (fp16, contiguous)
__device__ int      g_lop[BSZ * RMAX];
__device__ int      g_rop[BSZ * RMAX];
__device__ int      g_nred[BSZ];
__device__ int      g_nredmax[4];
__device__ int      g_top[BSZ];
__device__ int      g_badR[RMAX];
__device__ int      g_anyBad;
__device__ unsigned g_bar4[4];

__device__ __forceinline__ float sigm(float x) { return 1.0f / (1.0f + expf(-x)); }

// ---------------- PTX helpers ----------------
__device__ __forceinline__ void cp16(uint32_t sdst, const void* gsrc) {
    asm volatile("cp.async.cg.shared.global [%0], [%1], 16;\n" :: "r"(sdst), "l"(gsrc));
}
__device__ __forceinline__ void cp_commit() { asm volatile("cp.async.commit_group;\n" ::); }
template <int N> __device__ __forceinline__ void cp_wait() {
    asm volatile("cp.async.wait_group %0;\n" :: "n"(N));
}
__device__ __forceinline__ void ldsm4(uint32_t* r, uint32_t addr) {
    asm volatile("ldmatrix.sync.aligned.m8n8.x4.shared.b16 {%0,%1,%2,%3},[%4];\n"
                 : "=r"(r[0]), "=r"(r[1]), "=r"(r[2]), "=r"(r[3]) : "r"(addr));
}
__device__ __forceinline__ void ldsm2(uint32_t& r0, uint32_t& r1, uint32_t addr) {
    asm volatile("ldmatrix.sync.aligned.m8n8.x2.shared.b16 {%0,%1},[%2];\n"
                 : "=r"(r0), "=r"(r1) : "r"(addr));
}
__device__ __forceinline__ void mma16816(float* c, const uint32_t* a, uint32_t b0, uint32_t b1) {
    asm volatile(
        "mma.sync.aligned.m16n8k16.row.col.f32.f16.f16.f32 "
        "{%0,%1,%2,%3},{%4,%5,%6,%7},{%8,%9},{%0,%1,%2,%3};\n"
        : "+f"(c[0]), "+f"(c[1]), "+f"(c[2]), "+f"(c[3])
        : "r"(a[0]), "r"(a[1]), "r"(a[2]), "r"(a[3]), "r"(b0), "r"(b1));
}
__device__ __forceinline__ void bar_arrive_release(unsigned* addr) {
    asm volatile("red.release.gpu.global.add.u32 [%0], %1;" :: "l"(addr), "r"(1u) : "memory");
}
__device__ __forceinline__ unsigned ld_relaxed(const unsigned* addr) {
    unsigned v;
    asm volatile("ld.relaxed.gpu.global.u32 %0, [%1];" : "=r"(v) : "l"(addr) : "memory");
    return v;
}
__device__ __forceinline__ unsigned ld_acquire(const unsigned* addr) {
    unsigned v;
    asm volatile("ld.acquire.gpu.global.u32 %0, [%1];" : "=r"(v) : "l"(addr) : "memory");
    return v;
}

// ---------------- setup: leaves->fp16 + zero slots ----------------
__global__ void setup_kernel(const float* __restrict__ buffers) {
    int bid = blockIdx.x, tid = threadIdx.x;
    if (bid < 8192) {
        int i4 = (bid * 256 + tid) * 4;
        int b = i4 >> 15, rem = i4 & 32767;
        int r = rem >> 9, j = rem & 511;
        float4 v = *(const float4*)(buffers + ((size_t)b << 16) + ((size_t)r << 10) + j);
        __half2 h0 = __floats2half2_rn(v.x, v.y);
        __half2 h1 = __floats2half2_rn(v.z, v.w);
        *(uint2*)&g_h[b][r][j] = make_uint2(*(uint32_t*)&h0, *(uint32_t*)&h1);
    } else {
        int i = (bid - 8192) * 256 + tid;
        int b = i >> 9, j = i & 511;
        g_h[b][128][j] = __half(0.0f);
        g_c[b][RMAX][j] = 0.0f;
    }
}

// ---------------- weights: fp32 -> fp16, gate-interleave + transpose ----------------
__global__ void convert_w_kernel(const float* __restrict__ Wl,
                                 const float* __restrict__ Wr,
                                 const float* __restrict__ bl) {
    __shared__ float tile[40][33];
    int tid = threadIdx.x;
    int dcb = blockIdx.x >> 5;
    int kb  = blockIdx.x & 31;
    int dc0 = dcb * 40, k0 = kb * 32, j0 = dcb * 8;
    for (int e = tid; e < 1280; e += 256) {
        int jj = e & 7, g = (e >> 3) % 5, k = e / 40;
        int sc = g * SZ + j0 + jj;
        int kk = k0 + k;
        float v = (kk < SZ) ? Wl[(size_t)kk * GN + sc] : Wr[(size_t)(kk - SZ) * GN + sc];
        tile[5 * jj + g][k] = v;
    }
    __syncthreads();
    for (int e = tid; e < 1280; e += 256) {
        int kk = e & 31, dcl = e >> 5;
        g_Wt[((size_t)(dc0 + dcl) << 10) + k0 + kk] = __float2half(tile[dcl][kk]);
    }
    if (kb == 0 && tid < 40) {
        int dc = dc0 + tid, j = dc / 5, g = dc % 5;
        g_bias[dc] = bl[g * SZ + j];
    }
}

// ---------------- schedule ----------------
__global__ void schedule_kernel(const int* __restrict__ trans, int T) {
    __shared__ int st[136][33];
    int lt = threadIdx.x;
    int b = blockIdx.x * 32 + lt;
    if (blockIdx.x == 0 && lt < 4) g_bar4[lt] = 0;
    for (int i = 0; i < 136; i++) st[i][lt] = 128;
    int ptr = 0, bptr = 0, nr = 0;
    for (int t = 0; t < T; t++) {
        int tr = trans[b * T + t];
        if (tr == 0) {
            int n = (bptr < NLEAF - 1) ? bptr : (NLEAF - 1);
            int wp = ptr; if (wp < 0) wp = 0; if (wp > 130) wp = 130;
            st[wp][lt] = n;
            ptr++; bptr++;
        } else if (tr == 1) {
            int lp = ptr - 2; if (lp < 0) lp = 0;
            int rp = ptr - 1; if (rp < 0) rp = 0;
            if (nr < RMAX) {
                int lv = st[lp][lt], rv = st[rp][lt];
                g_lop[(b << 6) + nr] = lv;
                g_rop[(b << 6) + nr] = rv;
                if (rv >= 64 && rv < 128) { atomicOr(&g_badR[nr], 1); atomicOr(&g_anyBad, 1); }
                st[lp][lt] = 64 + nr;
                nr++;
            }
            ptr--;
        }
    }
    for (int i = nr; i < RMAX; i++) {
        g_lop[(b << 6) + i] = 128;
        g_rop[(b << 6) + i] = 128;
    }
    g_nred[b] = nr;
    atomicMax(&g_nredmax[b >> 6], nr);
    int tp = ptr - 1; if (tp < 0) tp = 0; if (tp > 130) tp = 130;
    g_top[b] = st[tp][lt];
}

// ---------------- PR precompute: PRh[row][dc] = leaf_h[row] @ Wr (fp16) ----------------
__global__ __launch_bounds__(256, 2) void pr_kernel() {
    extern __shared__ __align__(16) char smem[];
    uint32_t sb = (uint32_t)__cvta_generic_to_shared(smem);
    int tid = threadIdx.x, warp = tid >> 5, lane = tid & 31;
    int wm = warp >> 1, wn = warp & 1;
    int wc = wn * 40;
    int row0 = blockIdx.y * 128, col0 = blockIdx.x * 80;

    auto issueA = [&](int s) {
        uint32_t base = sb + PRA + (uint32_t)(s % 3) * PRASTG;
        #pragma unroll
        for (int j = 0; j < 2; j++) {
            int idx = tid + j * 256;
            int r = idx >> 2, c = idx & 3;
            int grow = row0 + r;
            cp16(base + (uint32_t)(r * 80 + c * 16),
                 &g_h[grow >> 6][grow & 63][s * 32 + c * 8]);
        }
    };

    for (int idx = tid; idx < 5120; idx += 256) {
        int r = idx >> 6, c = idx & 63;
        cp16(sb + PRB + (uint32_t)(r * 1024 + (((c ^ (r & 7)) << 4))),
             (const char*)g_Wt + ((size_t)(col0 + r) << 11) + 1024 + c * 16);
    }
    issueA(0); cp_commit();
    issueA(1); cp_commit();

    float acc[2][5][4];
    #pragma unroll
    for (int su = 0; su < 2; su++)
        #pragma unroll
        for (int f = 0; f < 5; f++)
            #pragma unroll
            for (int q = 0; q < 4; q++) acc[su][f][q] = 0.0f;

    int fr0 = wm * 32 + (lane & 7) + ((lane >> 3) & 1) * 8;
    int fr1 = fr0 + 16;
    int sel4 = (lane >> 4) & 1, sel3 = (lane >> 3) & 1;

    for (int s = 0; s < 16; s++) {
        cp_wait<1>();
        __syncthreads();
        uint32_t ab = sb + PRA + (uint32_t)(s % 3) * PRASTG;
        #pragma unroll
        for (int i = 0; i < 2; i++) {
            int ca = i * 2 + sel4;
            uint32_t a0[4], a1[4];
            ldsm4(a0, ab + (uint32_t)(fr0 * 80 + ca * 16));
            ldsm4(a1, ab + (uint32_t)(fr1 * 80 + ca * 16));
            int cbu = (s * 2 + i) * 2 + sel3;
            int br01 = wc + (0 + sel4) * 8 + (lane & 7);
            int br23 = wc + (2 + sel4) * 8 + (lane & 7);
            int br4  = wc + 32 + (lane & 7);
            uint32_t b01[4], b23[4], b4a, b4b;
            ldsm4(b01, sb + PRB + (uint32_t)(br01 * 1024 + (((cbu ^ (br01 & 7)) << 4))));
            ldsm4(b23, sb + PRB + (uint32_t)(br23 * 1024 + (((cbu ^ (br23 & 7)) << 4))));
            ldsm2(b4a, b4b, sb + PRB + (uint32_t)(br4 * 1024 + (((cbu ^ (br4 & 7)) << 4))));
            mma16816(acc[0][0], a0, b01[0], b01[1]); mma16816(acc[1][0], a1, b01[0], b01[1]);
            mma16816(acc[0][1], a0, b01[2], b01[3]); mma16816(acc[1][1], a1, b01[2], b01[3]);
            mma16816(acc[0][2], a0, b23[0], b23[1]); mma16816(acc[1][2], a1, b23[0], b23[1]);
            mma16816(acc[0][3], a0, b23[2], b23[3]); mma16816(acc[1][3], a1, b23[2], b23[3]);
            mma16816(acc[0][4], a0, b4a, b4b);       mma16816(acc[1][4], a1, b4a, b4b);
        }
        if (s + 2 < 16) issueA(s + 2);
        cp_commit();
    }
    cp_wait<0>();

    int gp = lane >> 2, t4 = lane & 3;
    #pragma unroll
    for (int su = 0; su < 2; su++)
        #pragma unroll
        for (int f = 0; f < 5; f++) {
            int r = row0 + wm * 32 + su * 16 + gp;
            int c = col0 + wc + f * 8 + t4 * 2;
            __half2 lo = __floats2half2_rn(acc[su][f][0], acc[su][f][1]);
            __half2 hi = __floats2half2_rn(acc[su][f][2], acc[su][f][3]);
            *(__half2*)&g_PRh[(size_t)r * GN + c]       = lo;
            *(__half2*)&g_PRh[(size_t)(r + 8) * GN + c] = hi;
        }
}

// ---------------- persistent SPINN kernel ----------------
// grid (32, 4) = 128 CTAs, 512 threads = 16 warps: kg(4) x wm(2) x wn(2)
__global__ __launch_bounds__(NTH, 1) void spinn_kernel(const float* __restrict__ buffers, int RL) {
    extern __shared__ __align__(16) char smem[];
    uint32_t sb = (uint32_t)__cvta_generic_to_shared(smem);
    int* s_lop = (int*)(smem + CTRL);          // [2][64]
    int* s_rop = (int*)(smem + CTRL + 512);    // [2][64]
    int* s_val = (int*)(smem + CTRL + 1024);   // [2][64]
    int* s_top = (int*)(smem + CTRL + 1536);   // [64]

    int tid = threadIdx.x, warp = tid >> 5, lane = tid & 31;
    int kg = warp >> 2, wm = (warp >> 1) & 1, wn = warp & 1;
    int wr = wm * 32, wc = wn * 40;
    int row0 = blockIdx.y * BM, col0 = blockIdx.x * BN;
    int by = blockIdx.y;

    // resident B1 (Wl) and B2 (Wr): 80 rows x 1024B each, XOR-8 swizzle
    for (int idx = tid; idx < 80 * 64; idx += NTH) {
        int r = idx >> 6, c = idx & 63;
        uint32_t dsw = (uint32_t)(r * 1024 + (((c ^ (r & 7)) << 4)));
        const char* src = (const char*)g_Wt + ((size_t)(col0 + r) << 11) + c * 16;
        cp16(sb + B1OFF + dsw, src);
        cp16(sb + B2OFF + dsw, src + 1024);
    }
    cp_commit(); cp_wait<0>();

    int RLg = g_nredmax[by];
    if (RLg > RL) RLg = RL;
    int gsInA = g_anyBad;                   // fallback schedules keep Gs in A region

    int jl = tid & 15;
    int jg0 = blockIdx.x * 16 + jl;
    float bias[5];
    #pragma unroll
    for (int g = 0; g < 5; g++) bias[g] = g_bias[col0 + jl * 5 + g];

    int arow = tid >> 3, ac0 = tid & 7;
    int fr0 = wr + (lane & 7) + ((lane >> 3) & 1) * 8;
    int fr1 = fr0 + 16;
    int sel4 = (lane >> 4) & 1, sel3 = (lane >> 3) & 1;
    int gp = lane >> 2, t4 = lane & 3;

    // Gs buffers: fast path in B2 (Wr region, unused) — lets kg>=2 warps dump
    // partials without waiting for the A-region-aliasing sync
    float (*Gs0)[84], (*Gs1)[84];
    if (gsInA) {
        Gs0 = (float (*)[84])smem;
        Gs1 = (float (*)[84])(smem + 32768);
    } else {
        Gs0 = (float (*)[84])(smem + B2OFF);
        Gs1 = (float (*)[84])(smem + B2OFF + 21504);
    }

    if (tid < 64) {
        int b = row0 + tid;
        s_lop[tid] = g_lop[b << 6];
        s_rop[tid] = g_rop[b << 6];
        s_val[tid] = (0 < g_nred[b]) ? 1 : 0;
        s_top[tid] = g_top[b];
    }
    __syncthreads();

    for (int k = 0; k < RLg; k++) {
        int par = k & 1;
        int skipf = (g_badR[k] == 0);

        // A load: two 32KB halves, separate commit groups
        auto loadA = [&](int useR) {
            int id = (useR ? s_rop : s_lop)[par * 64 + arow];
            const __half* src = &g_h[row0 + arow][id][0];
            #pragma unroll
            for (int j = 0; j < 4; j++) {
                int c = ac0 + j * 8;
                cp16(sb + AOFF + (uint32_t)(arow * 1024 + (((c ^ (arow & 7)) << 4))),
                     src + c * 8);
            }
            cp_commit();
            #pragma unroll
            for (int j = 4; j < 8; j++) {
                int c = ac0 + j * 8;
                cp16(sb + AOFF + (uint32_t)(arow * 1024 + (((c ^ (arow & 7)) << 4))),
                     src + c * 8);
            }
            cp_commit();
        };

        loadA(0);

        // ---- prefetch epilogue operands (latency hidden behind GEMM) ----
        float lcv[2], rcv[2], tab[2][5];
        #pragma unroll
        for (int i = 0; i < 2; i++) {
            int r = (tid >> 4) + 32 * i;
            int b = row0 + r;
            int lid = s_lop[par * 64 + r], rid = s_rop[par * 64 + r];
            lcv[i] = (lid < 64) ? buffers[((size_t)b << 16) + ((size_t)lid << 10) + SZ + jg0]
                                : g_c[b][(lid == 128) ? RMAX : (lid - 64)][jg0];
            rcv[i] = (rid < 64) ? buffers[((size_t)b << 16) + ((size_t)rid << 10) + SZ + jg0]
                                : g_c[b][(rid == 128) ? RMAX : (rid - 64)][jg0];
            #pragma unroll
            for (int g = 0; g < 5; g++) tab[i][g] = 0.0f;
            if (skipf && rid < 64) {
                const __half* tp = &g_PRh[((size_t)((b << 6) + rid)) * GN + col0 + jl * 5];
                #pragma unroll
                for (int g = 0; g < 5; g++) tab[i][g] = __half2float(tp[g]);
            }
        }

        // ---- next-step id tables (static schedule; overlap with GEMM) ----
        if (tid < 64) {
            int kn = k + 1;
            int b = row0 + tid;
            int lop = 128, rop = 128, vv = 0;
            if (kn < RMAX) {
                lop = g_lop[(b << 6) + kn];
                rop = g_rop[(b << 6) + kn];
                vv  = (kn < g_nred[b]) ? 1 : 0;
            }
            int np = par ^ 1;
            s_lop[np * 64 + tid] = lop;
            s_rop[np * 64 + tid] = rop;
            s_val[np * 64 + tid] = vv;
        }

        float acc[2][5][4];
        #pragma unroll
        for (int su = 0; su < 2; su++)
            #pragma unroll
            for (int f = 0; f < 5; f++)
                #pragma unroll
                for (int q = 0; q < 4; q++) acc[su][f][q] = 0.0f;

        // K-chunk map: ca = i*8 + kg*2 + sel — every kg owns chunks in both halves
        auto pass = [&](uint32_t boff, int i0, int i1) {
            #pragma unroll
            for (int i = i0; i < i1; i++) {
                int ca = i * 8 + kg * 2 + sel4;
                uint32_t a0[4], a1[4];
                ldsm4(a0, sb + AOFF + (uint32_t)(fr0 * 1024 + (((ca ^ (fr0 & 7)) << 4))));
                ldsm4(a1, sb + AOFF + (uint32_t)(fr1 * 1024 + (((ca ^ (fr1 & 7)) << 4))));
                int cbu = i * 8 + kg * 2 + sel3;
                int br01 = wc + (0 + sel4) * 8 + (lane & 7);
                int br23 = wc + (2 + sel4) * 8 + (lane & 7);
                int br4  = wc + 32 + (lane & 7);
                uint32_t b01[4], b23[4], b4a, b4b;
                ldsm4(b01, sb + boff + (uint32_t)(br01 * 1024 + (((cbu ^ (br01 & 7)) << 4))));
                ldsm4(b23, sb + boff + (uint32_t)(br23 * 1024 + (((cbu ^ (br23 & 7)) << 4))));
                ldsm2(b4a, b4b, sb + boff + (uint32_t)(br4 * 1024 + (((cbu ^ (br4 & 7)) << 4))));
                mma16816(acc[0][0], a0, b01[0], b01[1]); mma16816(acc[1][0], a1, b01[0], b01[1]);
                mma16816(acc[0][1], a0, b01[2], b01[3]); mma16816(acc[1][1], a1, b01[2], b01[3]);
                mma16816(acc[0][2], a0, b23[0], b23[1]); mma16816(acc[1][2], a1, b23[0], b23[1]);
                mma16816(acc[0][3], a0, b23[2], b23[3]); mma16816(acc[1][3], a1, b23[2], b23[3]);
                mma16816(acc[0][4], a0, b4a, b4b);       mma16816(acc[1][4], a1, b4a, b4b);
            }
        };

        // half0 compute overlaps half1 in-flight
        cp_wait<1>();
        __syncthreads();
        pass(B1OFF, 0, 4);
        cp_wait<0>();
        __syncthreads();
        pass(B1OFF, 4, 8);

        if (!skipf) {                    // generic fallback: rh @ Wr in-step
            __syncthreads();
            loadA(1);
            cp_wait<0>();
            __syncthreads();
            pass(B2OFF, 0, 8);
        }

        // ---- K-split reduction ----
        if (gsInA) __syncthreads();      // only needed when Gs aliases A (fallback mode)
        if (kg >= 2) {
            float (*G)[84] = (kg == 3) ? Gs0 : Gs1;
            #pragma unroll
            for (int su = 0; su < 2; su++)
                #pragma unroll
                for (int f = 0; f < 5; f++) {
                    int rr = wr + su * 16 + gp, cc = wc + f * 8 + t4 * 2;
                    G[rr][cc]         = acc[su][f][0];
                    G[rr][cc + 1]     = acc[su][f][1];
                    G[rr + 8][cc]     = acc[su][f][2];
                    G[rr + 8][cc + 1] = acc[su][f][3];
                }
        }
        __syncthreads();
        if (kg < 2) {
            float (*G)[84] = (kg == 1) ? Gs0 : Gs1;
            #pragma unroll
            for (int su = 0; su < 2; su++)
                #pragma unroll
                for (int f = 0; f < 5; f++) {
                    int rr = wr + su * 16 + gp, cc = wc + f * 8 + t4 * 2;
                    G[rr][cc]         += acc[su][f][0];
                    G[rr][cc + 1]     += acc[su][f][1];
                    G[rr + 8][cc]     += acc[su][f][2];
                    G[rr + 8][cc + 1] += acc[su][f][3];
                }
        }
        __syncthreads();

        // ---- LSTM epilogue ----
        #pragma unroll
        for (int i = 0; i < 2; i++) {
            int r = (tid >> 4) + 32 * i;
            if (s_val[par * 64 + r]) {
                int b  = row0 + r;
                int cb = jl * 5;
                float a  = Gs0[r][cb + 0] + Gs1[r][cb + 0] + bias[0] + tab[i][0];
                float ii = Gs0[r][cb + 1] + Gs1[r][cb + 1] + bias[1] + tab[i][1];
                float f1 = Gs0[r][cb + 2] + Gs1[r][cb + 2] + bias[2] + tab[i][2];
                float f2 = Gs0[r][cb + 3] + Gs1[r][cb + 3] + bias[3] + tab[i][3];
                float o  = Gs0[r][cb + 4] + Gs1[r][cb + 4] + bias[4] + tab[i][4];
                float cc = tanhf(a) * sigm(ii) + sigm(f1) * lcv[i] + sigm(f2) * rcv[i];
                float hh = sigm(o) * tanhf(cc);
                g_h[b][64 + k][jg0] = __float2half(hh);
                g_c[b][k][jg0]      = cc;
                if (s_top[r] == 64 + k) g_hf[b][k][jg0] = hh;   // only the final top is read
            }
        }

        // ---- row-group barrier: release arrival + acquire poll ----
        __syncthreads();
        if (tid == 0) {
            bar_arrive_release(&g_bar4[by]);
            unsigned tgt = (unsigned)(32 * (k + 1));
            while (ld_relaxed(&g_bar4[by]) < tgt) { }
            (void)ld_acquire(&g_bar4[by]);
        }
        __syncthreads();
    }
}

// ---------------- final gather ----------------
__global__ void final_kernel(const float* __restrict__ buffers, float* __restrict__ out) {
    int i = blockIdx.x * blockDim.x + threadIdx.x;
    if (i >= BSZ * SZ) return;
    int b = i / SZ, j = i % SZ;
    int op = g_top[b];
    float v;
    if (op < 64)       v = buffers[((size_t)b << 16) + ((size_t)op << 10) + j];
    else if (op < 128) v = g_hf[b][op - 64][j];
    else               v = 0.0f;
    out[i] = v;
}

// ---------------- launch ----------------
extern "C" void kernel_launch(void* const* d_in, const int* in_sizes, int n_in,
                              void* d_out, int out_size) {
    const float* buffers = (const float*)d_in[0];
    const int*   trans   = (const int*)d_in[1];
    const float* Wl      = (const float*)d_in[2];
    const float* Wr      = (const float*)d_in[3];
    const float* bl      = (const float*)d_in[4];
    float*       out     = (float*)d_out;

    int T  = in_sizes[1] / BSZ;
    int RL = (T + 1) / 2;
    if (RL > RMAX) RL = RMAX;

    static int attr_done = 0;
    if (!attr_done) {
        cudaFuncSetAttribute(spinn_kernel, cudaFuncAttributeMaxDynamicSharedMemorySize,
                             SMEM_TOTAL);
        cudaFuncSetAttribute(pr_kernel, cudaFuncAttributeMaxDynamicSharedMemorySize,
                             PR_SMEM);
        attr_done = 1;
    }

    schedule_kernel<<<8, 32>>>(trans, T);
    setup_kernel<<<8192 + 512, 256>>>(buffers);
    convert_w_kernel<<<2048, 256>>>(Wl, Wr, bl);

    dim3 prgrid(GN / 80, (BSZ * NLEAF) / 128);    // (32, 128)
    pr_kernel<<<prgrid, 256, PR_SMEM>>>();

    dim3 grid(GN / BN, BSZ / BM);                 // (32, 4) = 128 CTAs
    spinn_kernel<<<grid, NTH, SMEM_TOTAL>>>(buffers, RL);

    final_kernel<<<(BSZ * SZ + 255) / 256, 256>>>(buffers, out);
}

// round 15
// speedup vs baseline: 1.2571x; 1.0511x over previous
#include <cuda_runtime.h>
#include <cuda_fp16.h>
#include <cstdint>
#include <math.h>

#define BSZ   256
#define NLEAF 64
#define SZ    512
#define D2    1024
#define GN    2560
#define RMAX  64

#define BM    64
#define BN    80
#define NTH   512

// spinn smem layout (bytes): A(64K, Gs fallback) | B1(Wl) | B2(Wr / Gs fast) | id tables
#define AOFF   0
#define B1OFF  65536
#define B2OFF  147456
#define CTRL   229376
#define SMEM_TOTAL (CTRL + 1792)     // 231168 <= 232448 opt-in max

// pr smem: 3 A stages (256 rows x 80B) + resident B (160 rows x 1024B)
#define PRA    0
#define PRASTG 20480
#define PRB    61440                 // 1024-aligned
#define PR_SMEM (PRB + 163840)       // 225280

// ---------------- device scratch ----------------
__device__ __half   g_h[BSZ][129][SZ];      // 0..63 leaves, 64..127 results, 128 zero
__device__ float    g_c[BSZ][RMAX + 1][SZ];
__device__ float    g_hf[BSZ][RMAX][SZ];
__device__ __half   g_Wt[(size_t)GN * D2];  // [dc][k] gate-interleaved, transposed
__device__ float    g_bias[GN];
__device__ __half   g_PRh[(size_t)BSZ * NLEAF * GN]; // leaf @ Wr (fp16, contiguous)
__device__ int      g_lop[BSZ * RMAX];
__device__ int      g_rop[BSZ * RMAX];
__device__ int      g_nred[BSZ];
__device__ int      g_nredmax[4];
__device__ int      g_top[BSZ];
__device__ int      g_badR[RMAX];
__device__ int      g_anyBad;
__device__ unsigned g_bar4[4];

__device__ __forceinline__ float sigm(float x) { return 1.0f / (1.0f + expf(-x)); }

// ---------------- PTX helpers ----------------
__device__ __forceinline__ void cp16(uint32_t sdst, const void* gsrc) {
    asm volatile("cp.async.cg.shared.global [%0], [%1], 16;\n" :: "r"(sdst), "l"(gsrc));
}
__device__ __forceinline__ void cp_commit() { asm volatile("cp.async.commit_group;\n" ::); }
template <int N> __device__ __forceinline__ void cp_wait() {
    asm volatile("cp.async.wait_group %0;\n" :: "n"(N));
}
__device__ __forceinline__ void ldsm4(uint32_t* r, uint32_t addr) {
    asm volatile("ldmatrix.sync.aligned.m8n8.x4.shared.b16 {%0,%1,%2,%3},[%4];\n"
                 : "=r"(r[0]), "=r"(r[1]), "=r"(r[2]), "=r"(r[3]) : "r"(addr));
}
__device__ __forceinline__ void ldsm2(uint32_t& r0, uint32_t& r1, uint32_t addr) {
    asm volatile("ldmatrix.sync.aligned.m8n8.x2.shared.b16 {%0,%1},[%2];\n"
                 : "=r"(r0), "=r"(r1) : "r"(addr));
}
__device__ __forceinline__ void mma16816(float* c, const uint32_t* a, uint32_t b0, uint32_t b1) {
    asm volatile(
        "mma.sync.aligned.m16n8k16.row.col.f32.f16.f16.f32 "
        "{%0,%1,%2,%3},{%4,%5,%6,%7},{%8,%9},{%0,%1,%2,%3};\n"
        : "+f"(c[0]), "+f"(c[1]), "+f"(c[2]), "+f"(c[3])
        : "r"(a[0]), "r"(a[1]), "r"(a[2]), "r"(a[3]), "r"(b0), "r"(b1));
}
__device__ __forceinline__ void bar_arrive_release(unsigned* addr) {
    asm volatile("red.release.gpu.global.add.u32 [%0], %1;" :: "l"(addr), "r"(1u) : "memory");
}
__device__ __forceinline__ unsigned ld_relaxed(const unsigned* addr) {
    unsigned v;
    asm volatile("ld.relaxed.gpu.global.u32 %0, [%1];" : "=r"(v) : "l"(addr) : "memory");
    return v;
}
__device__ __forceinline__ unsigned ld_acquire(const unsigned* addr) {
    unsigned v;
    asm volatile("ld.acquire.gpu.global.u32 %0, [%1];" : "=r"(v) : "l"(addr) : "memory");
    return v;
}

// ---------------- fused prelude: setup | convert_w | schedule (independent) ----------------
// blocks [0,8704): leaves->fp16 + zero slots
// blocks [8704,10752): weight convert/interleave/transpose
// blocks [10752,10760): per-batch symbolic stack schedule (32 lanes)
__global__ void prelude_kernel(const float* __restrict__ buffers,
                               const float* __restrict__ Wl,
                               const float* __restrict__ Wr,
                               const float* __restrict__ bl,
                               const int* __restrict__ trans, int T) {
    __shared__ int shm[136 * 33];            // union: schedule stacks / convert tile
    int bid = blockIdx.x, tid = threadIdx.x;

    if (bid < 8704) {                        // ---- setup ----
        if (bid < 8192) {
            int i4 = (bid * 256 + tid) * 4;
            int b = i4 >> 15, rem = i4 & 32767;
            int r = rem >> 9, j = rem & 511;
            float4 v = *(const float4*)(buffers + ((size_t)b << 16) + ((size_t)r << 10) + j);
            __half2 h0 = __floats2half2_rn(v.x, v.y);
            __half2 h1 = __floats2half2_rn(v.z, v.w);
            *(uint2*)&g_h[b][r][j] = make_uint2(*(uint32_t*)&h0, *(uint32_t*)&h1);
        } else {
            int i = (bid - 8192) * 256 + tid;
            int b = i >> 9, j = i & 511;
            g_h[b][128][j] = __half(0.0f);
            g_c[b][RMAX][j] = 0.0f;
        }
    } else if (bid < 10752) {                // ---- convert_w ----
        float (*tile)[33] = (float (*)[33])shm;
        int bx = bid - 8704;
        int dcb = bx >> 5, kb = bx & 31;
        int dc0 = dcb * 40, k0 = kb * 32, j0 = dcb * 8;
        for (int e = tid; e < 1280; e += 256) {
            int jj = e & 7, g = (e >> 3) % 5, k = e / 40;
            int sc = g * SZ + j0 + jj;
            int kk = k0 + k;
            float v = (kk < SZ) ? Wl[(size_t)kk * GN + sc] : Wr[(size_t)(kk - SZ) * GN + sc];
            tile[5 * jj + g][k] = v;
        }
        __syncthreads();
        for (int e = tid; e < 1280; e += 256) {
            int kk = e & 31, dcl = e >> 5;
            g_Wt[((size_t)(dc0 + dcl) << 10) + k0 + kk] = __float2half(tile[dcl][kk]);
        }
        if (kb == 0 && tid < 40) {
            int dc = dc0 + tid, j = dc / 5, g = dc % 5;
            g_bias[dc] = bl[g * SZ + j];
        }
    } else {                                 // ---- schedule ----
        int bx = bid - 10752;
        int lt = tid;
        if (lt >= 32) return;
        int b = bx * 32 + lt;
        int (*st)[33] = (int (*)[33])shm;
        if (bx == 0 && lt < 4) g_bar4[lt] = 0;
        for (int i = 0; i < 136; i++) st[i][lt] = 128;
        int ptr = 0, bptr = 0, nr = 0;
        for (int t = 0; t < T; t++) {
            int tr = trans[b * T + t];
            if (tr == 0) {
                int n = (bptr < NLEAF - 1) ? bptr : (NLEAF - 1);
                int wp = ptr; if (wp < 0) wp = 0; if (wp > 130) wp = 130;
                st[wp][lt] = n;
                ptr++; bptr++;
            } else if (tr == 1) {
                int lp = ptr - 2; if (lp < 0) lp = 0;
                int rp = ptr - 1; if (rp < 0) rp = 0;
                if (nr < RMAX) {
                    int lv = st[lp][lt], rv = st[rp][lt];
                    g_lop[(b << 6) + nr] = lv;
                    g_rop[(b << 6) + nr] = rv;
                    if (rv >= 64 && rv < 128) { atomicOr(&g_badR[nr], 1); atomicOr(&g_anyBad, 1); }
                    st[lp][lt] = 64 + nr;
                    nr++;
                }
                ptr--;
            }
        }
        for (int i = nr; i < RMAX; i++) {
            g_lop[(b << 6) + i] = 128;
            g_rop[(b << 6) + i] = 128;
        }
        g_nred[b] = nr;
        atomicMax(&g_nredmax[b >> 6], nr);
        int tp = ptr - 1; if (tp < 0) tp = 0; if (tp > 130) tp = 130;
        g_top[b] = st[tp][lt];
    }
}

// ---------------- PR precompute: PRh[row][dc] = leaf_h[row] @ Wr (fp16) ----------------
// grid (16, 64), 512 thr, 16 warps 4m x 4n, tile 256 x 160, K=512, 1 CTA/SM
__global__ __launch_bounds__(512, 1) void pr_kernel() {
    extern __shared__ __align__(16) char smem[];
    uint32_t sb = (uint32_t)__cvta_generic_to_shared(smem);
    int tid = threadIdx.x, warp = tid >> 5, lane = tid & 31;
    int wm = warp >> 2;                  // 0..3 (64-row warp tiles)
    int wn = warp & 3;                   // 0..3 (40-col warp tiles)
    int wc = wn * 40;
    int row0 = blockIdx.y * 256, col0 = blockIdx.x * 160;

    auto issueA = [&](int s) {           // stage: 256 rows x 32 halfs at 80B stride
        uint32_t base = sb + PRA + (uint32_t)(s % 3) * PRASTG;
        #pragma unroll
        for (int j = 0; j < 2; j++) {
            int idx = tid + j * 512;
            int r = idx >> 2, c = idx & 3;
            int grow = row0 + r;
            cp16(base + (uint32_t)(r * 80 + c * 16),
                 &g_h[grow >> 6][grow & 63][s * 32 + c * 8]);
        }
    };

    // resident B (Wr half, k 512..1023): 160 rows x 1024B, XOR-8 swizzle
    for (int idx = tid; idx < 160 * 64; idx += 512) {
        int r = idx >> 6, c = idx & 63;
        cp16(sb + PRB + (uint32_t)(r * 1024 + (((c ^ (r & 7)) << 4))),
             (const char*)g_Wt + ((size_t)(col0 + r) << 11) + 1024 + c * 16);
    }
    issueA(0); cp_commit();
    issueA(1); cp_commit();

    float acc[4][5][4];
    #pragma unroll
    for (int su = 0; su < 4; su++)
        #pragma unroll
        for (int f = 0; f < 5; f++)
            #pragma unroll
            for (int q = 0; q < 4; q++) acc[su][f][q] = 0.0f;

    int frb = wm * 64 + (lane & 7) + ((lane >> 3) & 1) * 8;   // + su*16
    int sel4 = (lane >> 4) & 1, sel3 = (lane >> 3) & 1;

    for (int s = 0; s < 16; s++) {
        cp_wait<1>();
        __syncthreads();
        uint32_t ab = sb + PRA + (uint32_t)(s % 3) * PRASTG;
        #pragma unroll
        for (int i = 0; i < 2; i++) {
            int ca = i * 2 + sel4;
            uint32_t a[4][4];
            #pragma unroll
            for (int su = 0; su < 4; su++)
                ldsm4(a[su], ab + (uint32_t)((frb + su * 16) * 80 + ca * 16));
            int cbu = (s * 2 + i) * 2 + sel3;
            int br01 = wc + (0 + sel4) * 8 + (lane & 7);
            int br23 = wc + (2 + sel4) * 8 + (lane & 7);
            int br4  = wc + 32 + (lane & 7);
            uint32_t b01[4], b23[4], b4a, b4b;
            ldsm4(b01, sb + PRB + (uint32_t)(br01 * 1024 + (((cbu ^ (br01 & 7)) << 4))));
            ldsm4(b23, sb + PRB + (uint32_t)(br23 * 1024 + (((cbu ^ (br23 & 7)) << 4))));
            ldsm2(b4a, b4b, sb + PRB + (uint32_t)(br4 * 1024 + (((cbu ^ (br4 & 7)) << 4))));
            #pragma unroll
            for (int su = 0; su < 4; su++) {
                mma16816(acc[su][0], a[su], b01[0], b01[1]);
                mma16816(acc[su][1], a[su], b01[2], b01[3]);
                mma16816(acc[su][2], a[su], b23[0], b23[1]);
                mma16816(acc[su][3], a[su], b23[2], b23[3]);
                mma16816(acc[su][4], a[su], b4a, b4b);
            }
        }
        if (s + 2 < 16) issueA(s + 2);
        cp_commit();
    }
    cp_wait<0>();

    int gp = lane >> 2, t4 = lane & 3;
    #pragma unroll
    for (int su = 0; su < 4; su++)
        #pragma unroll
        for (int f = 0; f < 5; f++) {
            int r = row0 + wm * 64 + su * 16 + gp;
            int c = col0 + wc + f * 8 + t4 * 2;
            __half2 lo = __floats2half2_rn(acc[su][f][0], acc[su][f][1]);
            __half2 hi = __floats2half2_rn(acc[su][f][2], acc[su][f][3]);
            *(__half2*)&g_PRh[(size_t)r * GN + c]       = lo;
            *(__half2*)&g_PRh[(size_t)(r + 8) * GN + c] = hi;
        }
}

// ---------------- persistent SPINN kernel ----------------
// grid (32, 4) = 128 CTAs, 512 threads = 16 warps: kg(4) x wm(2) x wn(2)
__global__ __launch_bounds__(NTH, 1) void spinn_kernel(const float* __restrict__ buffers, int RL) {
    extern __shared__ __align__(16) char smem[];
    uint32_t sb = (uint32_t)__cvta_generic_to_shared(smem);
    int* s_lop = (int*)(smem + CTRL);          // [2][64]
    int* s_rop = (int*)(smem + CTRL + 512);    // [2][64]
    int* s_val = (int*)(smem + CTRL + 1024);   // [2][64]
    int* s_top = (int*)(smem + CTRL + 1536);   // [64]

    int tid = threadIdx.x, warp = tid >> 5, lane = tid & 31;
    int kg = warp >> 2, wm = (warp >> 1) & 1, wn = warp & 1;
    int wr = wm * 32, wc = wn * 40;
    int row0 = blockIdx.y * BM, col0 = blockIdx.x * BN;
    int by = blockIdx.y;

    // resident B1 (Wl) and B2 (Wr): 80 rows x 1024B each, XOR-8 swizzle
    for (int idx = tid; idx < 80 * 64; idx += NTH) {
        int r = idx >> 6, c = idx & 63;
        uint32_t dsw = (uint32_t)(r * 1024 + (((c ^ (r & 7)) << 4)));
        const char* src = (const char*)g_Wt + ((size_t)(col0 + r) << 11) + c * 16;
        cp16(sb + B1OFF + dsw, src);
        cp16(sb + B2OFF + dsw, src + 1024);
    }
    cp_commit(); cp_wait<0>();

    int RLg = g_nredmax[by];
    if (RLg > RL) RLg = RL;
    int gsInA = g_anyBad;                   // fallback schedules keep Gs in A region

    int jl = tid & 15;
    int jg0 = blockIdx.x * 16 + jl;
    float bias[5];
    #pragma unroll
    for (int g = 0; g < 5; g++) bias[g] = g_bias[col0 + jl * 5 + g];

    int arow = tid >> 3, ac0 = tid & 7;
    int fr0 = wr + (lane & 7) + ((lane >> 3) & 1) * 8;
    int fr1 = fr0 + 16;
    int sel4 = (lane >> 4) & 1, sel3 = (lane >> 3) & 1;
    int gp = lane >> 2, t4 = lane & 3;

    // Gs buffers: fast path in B2 (Wr region, unused) — lets kg>=2 warps dump
    // partials without waiting for the A-region-aliasing sync
    float (*Gs0)[84], (*Gs1)[84];
    if (gsInA) {
        Gs0 = (float (*)[84])smem;
        Gs1 = (float (*)[84])(smem + 32768);
    } else {
        Gs0 = (float (*)[84])(smem + B2OFF);
        Gs1 = (float (*)[84])(smem + B2OFF + 21504);
    }

    if (tid < 64) {
        int b = row0 + tid;
        s_lop[tid] = g_lop[b << 6];
        s_rop[tid] = g_rop[b << 6];
        s_val[tid] = (0 < g_nred[b]) ? 1 : 0;
        s_top[tid] = g_top[b];
    }
    __syncthreads();

    for (int k = 0; k < RLg; k++) {
        int par = k & 1;
        int skipf = (g_badR[k] == 0);

        // A load: two 32KB halves, separate commit groups
        auto loadA = [&](int useR) {
            int id = (useR ? s_rop : s_lop)[par * 64 + arow];
            const __half* src = &g_h[row0 + arow][id][0];
            #pragma unroll
            for (int j = 0; j < 4; j++) {
                int c = ac0 + j * 8;
                cp16(sb + AOFF + (uint32_t)(arow * 1024 + (((c ^ (arow & 7)) << 4))),
                     src + c * 8);
            }
            cp_commit();
            #pragma unroll
            for (int j = 4; j < 8; j++) {
                int c = ac0 + j * 8;
                cp16(sb + AOFF + (uint32_t)(arow * 1024 + (((c ^ (arow & 7)) << 4))),
                     src + c * 8);
            }
            cp_commit();
        };

        loadA(0);

        // ---- prefetch epilogue operands (latency hidden behind GEMM) ----
        float lcv[2], rcv[2], tab[2][5];
        #pragma unroll
        for (int i = 0; i < 2; i++) {
            int r = (tid >> 4) + 32 * i;
            int b = row0 + r;
            int lid = s_lop[par * 64 + r], rid = s_rop[par * 64 + r];
            lcv[i] = (lid < 64) ? buffers[((size_t)b << 16) + ((size_t)lid << 10) + SZ + jg0]
                                : g_c[b][(lid == 128) ? RMAX : (lid - 64)][jg0];
            rcv[i] = (rid < 64) ? buffers[((size_t)b << 16) + ((size_t)rid << 10) + SZ + jg0]
                                : g_c[b][(rid == 128) ? RMAX : (rid - 64)][jg0];
            #pragma unroll
            for (int g = 0; g < 5; g++) tab[i][g] = 0.0f;
            if (skipf && rid < 64) {
                const __half* tp = &g_PRh[((size_t)((b << 6) + rid)) * GN + col0 + jl * 5];
                #pragma unroll
                for (int g = 0; g < 5; g++) tab[i][g] = __half2float(tp[g]);
            }
        }

        // ---- next-step id tables (static schedule; overlap with GEMM) ----
        if (tid < 64) {
            int kn = k + 1;
            int b = row0 + tid;
            int lop = 128, rop = 128, vv = 0;
            if (kn < RMAX) {
                lop = g_lop[(b << 6) + kn];
                rop = g_rop[(b << 6) + kn];
                vv  = (kn < g_nred[b]) ? 1 : 0;
            }
            int np = par ^ 1;
            s_lop[np * 64 + tid] = lop;
            s_rop[np * 64 + tid] = rop;
            s_val[np * 64 + tid] = vv;
        }

        float acc[2][5][4];
        #pragma unroll
        for (int su = 0; su < 2; su++)
            #pragma unroll
            for (int f = 0; f < 5; f++)
                #pragma unroll
                for (int q = 0; q < 4; q++) acc[su][f][q] = 0.0f;

        // K-chunk map: ca = i*8 + kg*2 + sel — every kg owns chunks in both halves
        auto pass = [&](uint32_t boff, int i0, int i1) {
            #pragma unroll
            for (int i = i0; i < i1; i++) {
                int ca = i * 8 + kg * 2 + sel4;
                uint32_t a0[4], a1[4];
                ldsm4(a0, sb + AOFF + (uint32_t)(fr0 * 1024 + (((ca ^ (fr0 & 7)) << 4))));
                ldsm4(a1, sb + AOFF + (uint32_t)(fr1 * 1024 + (((ca ^ (fr1 & 7)) << 4))));
                int cbu = i * 8 + kg * 2 + sel3;
                int br01 = wc + (0 + sel4) * 8 + (lane & 7);
                int br23 = wc + (2 + sel4) * 8 + (lane & 7);
                int br4  = wc + 32 + (lane & 7);
                uint32_t b01[4], b23[4], b4a, b4b;
                ldsm4(b01, sb + boff + (uint32_t)(br01 * 1024 + (((cbu ^ (br01 & 7)) << 4))));
                ldsm4(b23, sb + boff + (uint32_t)(br23 * 1024 + (((cbu ^ (br23 & 7)) << 4))));
                ldsm2(b4a, b4b, sb + boff + (uint32_t)(br4 * 1024 + (((cbu ^ (br4 & 7)) << 4))));
                mma16816(acc[0][0], a0, b01[0], b01[1]); mma16816(acc[1][0], a1, b01[0], b01[1]);
                mma16816(acc[0][1], a0, b01[2], b01[3]); mma16816(acc[1][1], a1, b01[2], b01[3]);
                mma16816(acc[0][2], a0, b23[0], b23[1]); mma16816(acc[1][2], a1, b23[0], b23[1]);
                mma16816(acc[0][3], a0, b23[2], b23[3]); mma16816(acc[1][3], a1, b23[2], b23[3]);
                mma16816(acc[0][4], a0, b4a, b4b);       mma16816(acc[1][4], a1, b4a, b4b);
            }
        };

        // half0 compute overlaps half1 in-flight
        cp_wait<1>();
        __syncthreads();
        pass(B1OFF, 0, 4);
        cp_wait<0>();
        __syncthreads();
        pass(B1OFF, 4, 8);

        if (!skipf) {                    // generic fallback: rh @ Wr in-step
            __syncthreads();
            loadA(1);
            cp_wait<0>();
            __syncthreads();
            pass(B2OFF, 0, 8);
        }

        // ---- K-split reduction ----
        if (gsInA) __syncthreads();      // only needed when Gs aliases A (fallback mode)
        if (kg >= 2) {
            float (*G)[84] = (kg == 3) ? Gs0 : Gs1;
            #pragma unroll
            for (int su = 0; su < 2; su++)
                #pragma unroll
                for (int f = 0; f < 5; f++) {
                    int rr = wr + su * 16 + gp, cc = wc + f * 8 + t4 * 2;
                    G[rr][cc]         = acc[su][f][0];
                    G[rr][cc + 1]     = acc[su][f][1];
                    G[rr + 8][cc]     = acc[su][f][2];
                    G[rr + 8][cc + 1] = acc[su][f][3];
                }
        }
        __syncthreads();
        if (kg < 2) {
            float (*G)[84] = (kg == 1) ? Gs0 : Gs1;
            #pragma unroll
            for (int su = 0; su < 2; su++)
                #pragma unroll
                for (int f = 0; f < 5; f++) {
                    int rr = wr + su * 16 + gp, cc = wc + f * 8 + t4 * 2;
                    G[rr][cc]         += acc[su][f][0];
                    G[rr][cc + 1]     += acc[su][f][1];
                    G[rr + 8][cc]     += acc[su][f][2];
                    G[rr + 8][cc + 1] += acc[su][f][3];
                }
        }
        __syncthreads();

        // ---- LSTM epilogue ----
        #pragma unroll
        for (int i = 0; i < 2; i++) {
            int r = (tid >> 4) + 32 * i;
            if (s_val[par * 64 + r]) {
                int b  = row0 + r;
                int cb = jl * 5;
                float a  = Gs0[r][cb + 0] + Gs1[r][cb + 0] + bias[0] + tab[i][0];
                float ii = Gs0[r][cb + 1] + Gs1[r][cb + 1] + bias[1] + tab[i][1];
                float f1 = Gs0[r][cb + 2] + Gs1[r][cb + 2] + bias[2] + tab[i][2];
                float f2 = Gs0[r][cb + 3] + Gs1[r][cb + 3] + bias[3] + tab[i][3];
                float o  = Gs0[r][cb + 4] + Gs1[r][cb + 4] + bias[4] + tab[i][4];
                float cc = tanhf(a) * sigm(ii) + sigm(f1) * lcv[i] + sigm(f2) * rcv[i];
                float hh = sigm(o) * tanhf(cc);
                g_h[b][64 + k][jg0] = __float2half(hh);
                g_c[b][k][jg0]      = cc;
                if (s_top[r] == 64 + k) g_hf[b][k][jg0] = hh;   // only the final top is read
            }
        }

        // ---- row-group barrier: release arrival + acquire poll ----
        __syncthreads();
        if (tid == 0) {
            bar_arrive_release(&g_bar4[by]);
            unsigned tgt = (unsigned)(32 * (k + 1));
            while (ld_relaxed(&g_bar4[by]) < tgt) { }
            (void)ld_acquire(&g_bar4[by]);
        }
        __syncthreads();
    }
}

// ---------------- final gather ----------------
__global__ void final_kernel(const float* __restrict__ buffers, float* __restrict__ out) {
    int i = blockIdx.x * blockDim.x + threadIdx.x;
    if (i >= BSZ * SZ) return;
    int b = i / SZ, j = i % SZ;
    int op = g_top[b];
    float v;
    if (op < 64)       v = buffers[((size_t)b << 16) + ((size_t)op << 10) + j];
    else if (op < 128) v = g_hf[b][op - 64][j];
    else               v = 0.0f;
    out[i] = v;
}

// ---------------- launch ----------------
extern "C" void kernel_launch(void* const* d_in, const int* in_sizes, int n_in,
                              void* d_out, int out_size) {
    const float* buffers = (const float*)d_in[0];
    const int*   trans   = (const int*)d_in[1];
    const float* Wl      = (const float*)d_in[2];
    const float* Wr      = (const float*)d_in[3];
    const float* bl      = (const float*)d_in[4];
    float*       out     = (float*)d_out;

    int T  = in_sizes[1] / BSZ;
    int RL = (T + 1) / 2;
    if (RL > RMAX) RL = RMAX;

    static int attr_done = 0;
    if (!attr_done) {
        cudaFuncSetAttribute(spinn_kernel, cudaFuncAttributeMaxDynamicSharedMemorySize,
                             SMEM_TOTAL);
        cudaFuncSetAttribute(pr_kernel, cudaFuncAttributeMaxDynamicSharedMemorySize,
                             PR_SMEM);
        attr_done = 1;
    }

    prelude_kernel<<<10760, 256>>>(buffers, Wl, Wr, bl, trans, T);

    dim3 prgrid(GN / 160, (BSZ * NLEAF) / 256);   // (16, 64)
    pr_kernel<<<prgrid, 512, PR_SMEM>>>();

    dim3 grid(GN / BN, BSZ / BM);                 // (32, 4) = 128 CTAs
    spinn_kernel<<<grid, NTH, SMEM_TOTAL>>>(buffers, RL);

    final_kernel<<<(BSZ * SZ + 255) / 256, 256>>>(buffers, out);
}